// round 1
// baseline (speedup 1.0000x reference)
#include <cuda_runtime.h>

#define FDIM 128
#define TNODES 4
#define THREADS 128
#define GRIDSZ 444
#define MAXN 50001
#define MAXE 1000000

// Scratch (device globals: allocation-free per harness rules)
__device__ unsigned int g_or;            // 0 => edge dtype is int64, nonzero => int32
__device__ int g_row_ptr[MAXN];          // CSR row pointers over sorted-u COO
__device__ int g_v[MAXE];                // v indices converted to int32

// ---------------------------------------------------------------------------
// Detect edge dtype. The first 2E 32-bit words cover: (int64) the u row as
// lo/hi pairs with hi==0 since u<50000, or (int32) the whole u,v array whose
// odd-index values are certainly not all zero.
__global__ void detect_k(const unsigned int* __restrict__ w, int E) {
    unsigned int local = 0;
    for (int i = blockIdx.x * blockDim.x + threadIdx.x; i < E;
         i += gridDim.x * blockDim.x)
        local |= w[2 * i + 1];
    if (local) atomicOr(&g_or, 1u);
}

// Convert v indices (second row of edge_index) to int32 scratch.
__global__ void convert_k(const void* __restrict__ edges, int E) {
    const bool is64 = (g_or == 0);
    const long long* e64 = (const long long*)edges;
    const int* e32 = (const int*)edges;
    for (int j = blockIdx.x * blockDim.x + threadIdx.x; j < E;
         j += gridDim.x * blockDim.x)
        g_v[j] = is64 ? (int)e64[E + j] : e32[E + j];
}

// Build CSR row_ptr by lower_bound binary search per node (u is sorted).
__global__ void rowptr_k(const void* __restrict__ edges, int E, int nN) {
    const bool is64 = (g_or == 0);
    const long long* e64 = (const long long*)edges;
    const int* e32 = (const int*)edges;
    int node = blockIdx.x * blockDim.x + threadIdx.x;
    if (node > nN) return;
    if (node == nN) { g_row_ptr[nN] = E; return; }
    int lo = 0, hi = E;
    long long key = (long long)node;
    while (lo < hi) {
        int mid = (lo + hi) >> 1;
        long long um = is64 ? e64[mid] : (long long)e32[mid];
        if (um < key) lo = mid + 1; else hi = mid;
    }
    g_row_ptr[node] = lo;
}

// ---------------------------------------------------------------------------
// Packed f32x2 helpers (Blackwell FFMA2 — PTX only, halves FMA issue count)
__device__ __forceinline__ void fma2(unsigned long long& acc,
                                     unsigned long long a,
                                     unsigned long long b) {
    asm("fma.rn.f32x2 %0, %1, %2, %0;" : "+l"(acc) : "l"(a), "l"(b));
}
__device__ __forceinline__ unsigned long long packf2(float lo, float hi) {
    unsigned long long r;
    asm("mov.b64 %0, {%1, %2};" : "=l"(r) : "f"(lo), "f"(hi));
    return r;
}
__device__ __forceinline__ float2 unpackf2(unsigned long long v) {
    float2 r;
    asm("mov.b64 {%0, %1}, %2;" : "=f"(r.x), "=f"(r.y) : "l"(v));
    return r;
}

// ---------------------------------------------------------------------------
// Fused kernel: per group of 4 nodes (one per warp):
//   agg[t][:] = sum over edges of node t of x[v][:]   (warp-per-node gather)
//   out[t][fo] = agg[t][:] . W[:][fo] + bias[fo]      (thread fo owns W column
//                                                      in 128 registers, FFMA2)
__global__ void __launch_bounds__(THREADS) fused_k(
    const float* __restrict__ x, const float* __restrict__ Wm,
    const float* __restrict__ bias, float* __restrict__ out, int nN) {
    __shared__ __align__(16) float agg[TNODES][FDIM];
    const int tid = threadIdx.x;
    const int warp = tid >> 5, lane = tid & 31;

    // Preload this thread's W column as 64 packed f32x2 pairs (128 regs).
    unsigned long long w2[FDIM / 2];
#pragma unroll
    for (int j = 0; j < FDIM / 2; j++)
        w2[j] = packf2(Wm[(2 * j) * FDIM + tid], Wm[(2 * j + 1) * FDIM + tid]);
    const float b = bias[tid];

    for (int base = blockIdx.x * TNODES; base < nN;
         base += gridDim.x * TNODES) {
        // ---- gather: warp `warp` aggregates node base+warp ----
        const int node = base + warp;
        float4 a4 = make_float4(0.f, 0.f, 0.f, 0.f);
        if (node < nN) {
            const int s = g_row_ptr[node];
            const int e = g_row_ptr[node + 1];
            const float4* __restrict__ xr = (const float4*)x;
#pragma unroll 4
            for (int j = s; j < e; j++) {
                const int v = g_v[j];
                const float4 xv = __ldg(&xr[(size_t)v * (FDIM / 4) + lane]);
                a4.x += xv.x; a4.y += xv.y; a4.z += xv.z; a4.w += xv.w;
            }
        }
        *(float4*)&agg[warp][lane * 4] = a4;
        __syncthreads();

        // ---- GEMM: thread tid computes output feature `tid` for 4 nodes ----
        unsigned long long acc[TNODES];
#pragma unroll
        for (int t = 0; t < TNODES; t++) acc[t] = 0ull;
#pragma unroll
        for (int q = 0; q < FDIM / 4; q++) {
            const unsigned long long wlo = w2[2 * q];
            const unsigned long long whi = w2[2 * q + 1];
#pragma unroll
            for (int t = 0; t < TNODES; t++) {
                const ulonglong2 a = *(const ulonglong2*)&agg[t][q * 4];
                fma2(acc[t], wlo, a.x);
                fma2(acc[t], whi, a.y);
            }
        }
#pragma unroll
        for (int t = 0; t < TNODES; t++) {
            const int n2 = base + t;
            if (n2 < nN) {
                const float2 p = unpackf2(acc[t]);
                out[(size_t)n2 * FDIM + tid] = p.x + p.y + b;
            }
        }
        __syncthreads();
    }
}

// ---------------------------------------------------------------------------
extern "C" void kernel_launch(void* const* d_in, const int* in_sizes, int n_in,
                              void* d_out, int out_size) {
    const float* x = (const float*)d_in[0];
    const void* edges = d_in[1];
    const float* W = (const float*)d_in[2];
    const float* bias = (const float*)d_in[3];
    float* out = (float*)d_out;

    const int nN = in_sizes[0] / FDIM;
    int E = in_sizes[1] / 2;
    if (E > MAXE) E = MAXE;

    void* g_or_ptr = nullptr;
    cudaGetSymbolAddress(&g_or_ptr, g_or);
    cudaMemsetAsync(g_or_ptr, 0, sizeof(unsigned int));

    detect_k<<<148, 256>>>((const unsigned int*)edges, E);
    convert_k<<<296, 256>>>(edges, E);
    rowptr_k<<<(nN + 1 + 255) / 256, 256>>>(edges, E, nN);
    fused_k<<<GRIDSZ, THREADS>>>(x, W, bias, out, nN);
}